// round 5
// baseline (speedup 1.0000x reference)
#include <cuda_runtime.h>
#include <cstdint>

#define B 256
#define L 128
#define F 256
#define S 512
#define BF (B*F)
#define G4F 1024

// ---- static device scratch (no allocation) ----
__device__ float g_Wc[G4F * F];     // combined W_ih+W_hh, permuted [nf*128+c][k], tf32-rounded
__device__ float g_WihT[G4F * F];   // [(nf*256+k)*128 + c]  (permuted c)
__device__ float g_WhhT[G4F * F];
__device__ float g_WiT[L * F];      // [k*256 + f]
__device__ float g_bc[G4F];         // permuted combined bias
__device__ float g_init[B * F];
__device__ float g_c1[B * F];

__device__ __forceinline__ float sigf(float x) { return 1.0f / (1.0f + expf(-x)); }
__device__ __forceinline__ float tanhfast(float x) {
    float r; asm("tanh.approx.f32 %0, %1;" : "=f"(r) : "f"(x)); return r;
}
__device__ __forceinline__ float sigfast(float x) { return 0.5f * tanhfast(0.5f * x) + 0.5f; }

__device__ __forceinline__ unsigned tf32r(float x) {
    unsigned u; asm("cvt.rna.tf32.f32 %0, %1;" : "=r"(u) : "f"(x)); return u;
}

// mbarrier helpers (cluster scope)
__device__ __forceinline__ void mbar_init(uint32_t mbar, uint32_t cnt) {
    asm volatile("mbarrier.init.shared.b64 [%0], %1;" :: "r"(mbar), "r"(cnt) : "memory");
}
__device__ __forceinline__ void mbar_wait_acq(uint32_t mbar, uint32_t parity) {
    asm volatile(
        "{\n\t.reg .pred P;\n"
        "WL%=:\n\t"
        "mbarrier.try_wait.parity.acquire.cluster.shared::cta.b64 P, [%0], %1, 0x989680;\n\t"
        "@P bra WD%=;\n\t"
        "bra WL%=;\n"
        "WD%=:\n\t}"
        :: "r"(mbar), "r"(parity) : "memory");
}
__device__ __forceinline__ void mbar_arrive_remote(uint32_t mbar_local, uint32_t rank) {
    asm volatile(
        "{\n\t.reg .b32 ra;\n\t"
        "mapa.shared::cluster.u32 ra, %0, %1;\n\t"
        "mbarrier.arrive.release.cluster.shared::cluster.b64 _, [ra];\n\t}"
        :: "r"(mbar_local), "r"(rank) : "memory");
}
__device__ __forceinline__ uint32_t mapa_u32(uint32_t local, uint32_t rank) {
    uint32_t r;
    asm("mapa.shared::cluster.u32 %0, %1, %2;" : "=r"(r) : "r"(local), "r"(rank));
    return r;
}
__device__ __forceinline__ void st_cluster_f2(uint32_t addr, float2 v) {
    asm volatile("st.shared::cluster.v2.b32 [%0], {%1, %2};"
                 :: "r"(addr), "r"(__float_as_uint(v.x)), "r"(__float_as_uint(v.y)) : "memory");
}

// ---- P0: weight prep ----
__global__ void prep_kernel(const float* __restrict__ Wih, const float* __restrict__ Whh,
                            const float* __restrict__ bih, const float* __restrict__ bhh,
                            const float* __restrict__ Wi) {
    int bid = blockIdx.x, tid = threadIdx.x;
    if (bid < 1024) {
        int r = bid, k = tid;
        int g = r >> 8;
        int jj = r & 255;
        int nf = jj >> 5;
        int j  = jj & 31;
        int c  = ((j >> 3) << 5) + (g << 3) + (j & 7);
        float wih = Wih[r * 256 + k];
        float whh = Whh[r * 256 + k];
        g_Wc[(nf * 128 + c) * 256 + k] = __uint_as_float(tf32r(wih + whh));
        g_WihT[(nf * 256 + k) * 128 + c] = wih;
        g_WhhT[(nf * 256 + k) * 128 + c] = whh;
        if (k == 0) g_bc[nf * 128 + c] = bih[r] + bhh[r];
    } else {
        int k = bid - 1024;
        int f = tid;
        g_WiT[k * 256 + f] = Wi[f * 128 + k];
    }
}

// ---- P1: init = elu(x @ Wi.T + bi) ----
__global__ void init_kernel(const float* __restrict__ x, const float* __restrict__ bi) {
    __shared__ float xs[32 * 128];
    int bid = blockIdx.x, tid = threadIdx.x;
    int bt = bid >> 2, ft = bid & 3;
    for (int i = tid; i < 32 * 128; i += 256)
        xs[i] = x[(bt * 32 + (i >> 7)) * 128 + (i & 127)];
    __syncthreads();
    int tx = tid & 15, ty = tid >> 4;
    int b0 = ty * 2;
    int f0 = ft * 64 + tx * 4;
    float acc[2][4] = {};
#pragma unroll 4
    for (int k = 0; k < 128; ++k) {
        float4 w = *(const float4*)&g_WiT[k * 256 + f0];
        float x0 = xs[b0 * 128 + k];
        float x1 = xs[(b0 + 1) * 128 + k];
        acc[0][0] += x0 * w.x; acc[0][1] += x0 * w.y; acc[0][2] += x0 * w.z; acc[0][3] += x0 * w.w;
        acc[1][0] += x1 * w.x; acc[1][1] += x1 * w.y; acc[1][2] += x1 * w.z; acc[1][3] += x1 * w.w;
    }
#pragma unroll
    for (int r = 0; r < 2; ++r)
#pragma unroll
        for (int cc = 0; cc < 4; ++cc) {
            float v = acc[r][cc] + bi[f0 + cc];
            v = (v > 0.0f) ? v : expm1f(v);
            g_init[(bt * 32 + b0 + r) * 256 + f0 + cc] = v;
        }
}

// ---- P2: step 0 (inp = last_feat, h = c = init) ----
__global__ void step0_kernel(const float* __restrict__ lf, float* __restrict__ d_out) {
    extern __shared__ float sm[];
    float* lfs = sm;
    float* ins = lfs + 16 * 256;
    float* wih = ins + 16 * 256;
    float* whh = wih + 64 * 128;
    int tid = threadIdx.x;
    int nf = blockIdx.x & 7, mbt = blockIdx.x >> 3;
    for (int i = tid; i < 16 * 256; i += 256) {
        int gi = (mbt * 16 + (i >> 8)) * 256 + (i & 255);
        lfs[i] = lf[gi];
        ins[i] = g_init[gi];
    }
    int tx = tid & 31, ty = tid >> 5;
    int c0 = tx * 4;
    float acc[2][4] = {};
    for (int kc = 0; kc < 4; ++kc) {
        __syncthreads();
        for (int i = tid; i < 64 * 128; i += 256) {
            int k = kc * 64 + (i >> 7), c = i & 127;
            wih[i] = g_WihT[(nf * 256 + k) * 128 + c];
            whh[i] = g_WhhT[(nf * 256 + k) * 128 + c];
        }
        __syncthreads();
#pragma unroll 4
        for (int k = 0; k < 64; ++k) {
            float4 a4 = *(const float4*)&wih[k * 128 + c0];
            float4 b4 = *(const float4*)&whh[k * 128 + c0];
#pragma unroll
            for (int e = 0; e < 2; ++e) {
                int b = ty + 8 * e;
                float lv = lfs[b * 256 + kc * 64 + k];
                float iv = ins[b * 256 + kc * 64 + k];
                acc[e][0] += lv * a4.x + iv * b4.x;
                acc[e][1] += lv * a4.y + iv * b4.y;
                acc[e][2] += lv * a4.z + iv * b4.z;
                acc[e][3] += lv * a4.w + iv * b4.w;
            }
        }
    }
    __syncthreads();
    float* gss = lfs;
#pragma unroll
    for (int e = 0; e < 2; ++e)
#pragma unroll
        for (int cc = 0; cc < 4; ++cc)
            gss[(ty + 8 * e) * 132 + c0 + cc] = acc[e][cc];
    __syncthreads();
#pragma unroll
    for (int e2 = 0; e2 < 2; ++e2) {
        int li = tid + 256 * e2;
        int b = li >> 5, j = li & 31;
        int cb = ((j >> 3) << 5) + (j & 7);
        float iv = gss[b * 132 + cb]      + g_bc[nf * 128 + cb];
        float fv = gss[b * 132 + cb + 8]  + g_bc[nf * 128 + cb + 8];
        float gv = gss[b * 132 + cb + 16] + g_bc[nf * 128 + cb + 16];
        float ov = gss[b * 132 + cb + 24] + g_bc[nf * 128 + cb + 24];
        float cp = ins[b * 256 + nf * 32 + j];
        float cn = sigf(fv) * cp + sigf(iv) * tanhf(gv);
        float hn = sigf(ov) * tanhf(cn);
        int gi = (mbt * 16 + b) * 256 + nf * 32 + j;
        g_c1[gi] = cn;
        d_out[gi] = hn;
    }
}

// ---- tf32 mma helper ----
__device__ __forceinline__ void mma8(float* d, const unsigned* a, unsigned b0, unsigned b1) {
    asm volatile(
        "mma.sync.aligned.m16n8k8.row.col.f32.tf32.tf32.f32 "
        "{%0,%1,%2,%3}, {%4,%5,%6,%7}, {%8,%9}, {%0,%1,%2,%3};"
        : "+f"(d[0]), "+f"(d[1]), "+f"(d[2]), "+f"(d[3])
        : "r"(a[0]), "r"(a[1]), "r"(a[2]), "r"(a[3]), "r"(b0), "r"(b1));
}

// ---- P3: persistent recurrence, t = 1..511 ----
// 128 CTAs x 256 thr, clusters of 8 (= batch group). mb = bid>>3 (16 rows), nf = bid&7.
// h exchange via DSMEM push + mbarrier; d_out write-only.
__global__ void __cluster_dims__(8, 1, 1) __launch_bounds__(256, 1)
lstm_kernel(float* __restrict__ d_out) {
    __shared__ float hs[2][16 * 260];            // double-buffered h tiles (tf32, mma layout)
    __shared__ float red[128 * 20];              // k-split partials
    __shared__ __align__(8) unsigned long long mbars[4];  // full0, full1, empty0, empty1

    int tid = threadIdx.x;
    int nf = blockIdx.x & 7, mb = blockIdx.x >> 3;
    int warp = tid >> 5, lane = tid & 31;
    int cg = warp & 3, ks = warp >> 2;
    int gID = lane >> 2, tig = lane & 3;

    uint32_t hs0  = (uint32_t)__cvta_generic_to_shared(&hs[0][0]);
    uint32_t mb0  = (uint32_t)__cvta_generic_to_shared(&mbars[0]);
    uint32_t full0 = mb0, full1 = mb0 + 8, emp0 = mb0 + 16, emp1 = mb0 + 24;

    if (tid == 0) {
        mbar_init(full0, 8); mbar_init(full1, 8);
        mbar_init(emp0, 8);  mbar_init(emp1, 8);
    }

    // B fragments in registers: warp covers cols [cg*32,+32), k in [ks*128,+128)
    unsigned breg[4][16][2];
#pragma unroll
    for (int nt = 0; nt < 4; ++nt)
#pragma unroll
        for (int kb = 0; kb < 16; ++kb) {
            const float* wp = &g_Wc[(nf * 128 + cg * 32 + nt * 8 + gID) * 256 + ks * 128 + kb * 8 + tig];
            breg[nt][kb][0] = __float_as_uint(wp[0]);
            breg[nt][kb][1] = __float_as_uint(wp[4]);
        }

    float bias[4][2];
#pragma unroll
    for (int nt = 0; nt < 4; ++nt) {
        float b0 = g_bc[nf * 128 + cg * 32 + nt * 8 + 2 * tig];
        float b1 = g_bc[nf * 128 + cg * 32 + nt * 8 + 2 * tig + 1];
        bias[nt][0] = ks ? 0.0f : b0;
        bias[nt][1] = ks ? 0.0f : b1;
    }

    float creg[4];
    uint32_t peer_hs[8];      // peer hs[0] base (DSMEM)
    uint32_t dst_off[2];      // per-thread byte offset of its float2 within an hs buffer
    if (ks == 0) {
#pragma unroll
        for (int rh = 0; rh < 2; ++rh) {
#pragma unroll
            for (int ff = 0; ff < 2; ++ff)
                creg[rh * 2 + ff] =
                    g_c1[(mb * 16 + gID + rh * 8) * 256 + nf * 32 + cg * 8 + 2 * tig + ff];
            dst_off[rh] = ((gID + rh * 8) * 260 + nf * 32 + cg * 8 + 2 * tig) * 4;
        }
#pragma unroll
        for (int p = 0; p < 8; ++p) peer_hs[p] = mapa_u32(hs0, p);
    }

    // fill hs[1] with h_1 from d_out (written by step0; stream-ordered)
    {
        const float* hsrc = d_out + (size_t)mb * 4096;
#pragma unroll
        for (int i = tid * 4; i < 4096; i += 1024) {
            float4 v = *(const float4*)(hsrc + i);
            v.x = __uint_as_float(tf32r(v.x)); v.y = __uint_as_float(tf32r(v.y));
            v.z = __uint_as_float(tf32r(v.z)); v.w = __uint_as_float(tf32r(v.w));
            *(float4*)&hs[1][(i >> 8) * 260 + (i & 255)] = v;
        }
    }
    __syncthreads();
    // cluster-wide: all mbarriers initialized before any remote op
    asm volatile("barrier.cluster.arrive.aligned;" ::: "memory");
    asm volatile("barrier.cluster.wait.aligned;" ::: "memory");

    unsigned fph[2] = {0u, 0u};   // full parities (consumer)
    unsigned eph[2] = {1u, 1u};   // empty parities (producer; first wait passes)

    for (int t = 1; t < 512; ++t) {
        int b = t & 1;
        if (t > 1) {
            mbar_wait_acq(b ? full1 : full0, fph[b]);
            fph[b] ^= 1u;
        }

        // gates = hs[b] @ Wc^T (this CTA's 32-col group x k-half)
        float acc[4][4];
#pragma unroll
        for (int nt = 0; nt < 4; ++nt) {
            acc[nt][0] = bias[nt][0]; acc[nt][1] = bias[nt][1];
            acc[nt][2] = bias[nt][0]; acc[nt][3] = bias[nt][1];
        }
        const float* hb = &hs[b][0];
#pragma unroll
        for (int kb = 0; kb < 16; ++kb) {
            int k0 = ks * 128 + kb * 8;
            unsigned a[4];
            a[0] = __float_as_uint(hb[gID * 260 + k0 + tig]);
            a[1] = __float_as_uint(hb[(gID + 8) * 260 + k0 + tig]);
            a[2] = __float_as_uint(hb[gID * 260 + k0 + 4 + tig]);
            a[3] = __float_as_uint(hb[(gID + 8) * 260 + k0 + 4 + tig]);
#pragma unroll
            for (int nt = 0; nt < 4; ++nt)
                mma8(acc[nt], a, breg[nt][kb][0], breg[nt][kb][1]);
        }

        if (ks == 1) {
            float* rp = &red[(cg * 32 + lane) * 20];
#pragma unroll
            for (int nt = 0; nt < 4; ++nt)
                *(float4*)(rp + nt * 4) = make_float4(acc[nt][0], acc[nt][1], acc[nt][2], acc[nt][3]);
        }
        __syncthreads();   // reads of hs[b] complete + red published

        // signal "buffer b free" to all producers (skip t=1: locally filled; skip t=511: no producer)
        if (tid == 128 && t >= 2 && t < 511) {
#pragma unroll
            for (int p = 0; p < 8; ++p) mbar_arrive_remote(b ? emp1 : emp0, p);
        }

        if (ks == 0) {
            const float* rp = &red[(cg * 32 + lane) * 20];
#pragma unroll
            for (int nt = 0; nt < 4; ++nt) {
                float4 r4 = *(const float4*)(rp + nt * 4);
                acc[nt][0] += r4.x; acc[nt][1] += r4.y;
                acc[nt][2] += r4.z; acc[nt][3] += r4.w;
            }

            float hn[2][2];
#pragma unroll
            for (int rh = 0; rh < 2; ++rh)
#pragma unroll
                for (int ff = 0; ff < 2; ++ff) {
                    int q = rh * 2 + ff;
                    float cn = sigfast(acc[1][q]) * creg[q] + sigfast(acc[0][q]) * tanhfast(acc[2][q]);
                    hn[rh][ff] = sigfast(acc[3][q]) * tanhfast(cn);
                    creg[q] = cn;
                }

            if (t < 511) {
                int b2 = (t + 1) & 1;
                // backpressure: all peers done reading hs[b2] (2-step slack; usually immediate)
                mbar_wait_acq(b2 ? emp1 : emp0, eph[b2]);
                eph[b2] ^= 1u;
                // push tf32-rounded h to every peer's hs[b2]
                uint32_t bufoff = (uint32_t)b2 * (16 * 260 * 4);
#pragma unroll
                for (int rh = 0; rh < 2; ++rh) {
                    float2 rv = make_float2(__uint_as_float(tf32r(hn[rh][0])),
                                            __uint_as_float(tf32r(hn[rh][1])));
#pragma unroll
                    for (int p = 0; p < 8; ++p)
                        st_cluster_f2(peer_hs[p] + bufoff + dst_off[rh], rv);
                }
            }

            // fp32 h to output
            float* dst = d_out + (size_t)t * BF + (size_t)mb * 4096;
#pragma unroll
            for (int rh = 0; rh < 2; ++rh)
                *(float2*)(dst + (gID + rh * 8) * 256 + nf * 32 + cg * 8 + 2 * tig) =
                    make_float2(hn[rh][0], hn[rh][1]);

            if (t < 511) {
                asm volatile("bar.sync 1, 128;" ::: "memory");   // all ks=0 pushes done
                if (tid == 0) {
                    int b2 = (t + 1) & 1;
#pragma unroll
                    for (int p = 0; p < 8; ++p) mbar_arrive_remote(b2 ? full1 : full0, p);
                }
            }
        }
    }

    asm volatile("barrier.cluster.arrive.aligned;" ::: "memory");
    asm volatile("barrier.cluster.wait.aligned;" ::: "memory");
}

extern "C" void kernel_launch(void* const* d_in, const int* in_sizes, int n_in,
                              void* d_out, int out_size) {
    const float* x   = (const float*)d_in[0];
    const float* lf  = (const float*)d_in[1];
    const float* Wi  = (const float*)d_in[2];
    const float* bi  = (const float*)d_in[3];
    const float* Wih = (const float*)d_in[4];
    const float* Whh = (const float*)d_in[5];
    const float* bih = (const float*)d_in[6];
    const float* bhh = (const float*)d_in[7];
    float* out = (float*)d_out;

    cudaFuncSetAttribute(step0_kernel, cudaFuncAttributeMaxDynamicSharedMemorySize, 98304);

    prep_kernel<<<1152, 256>>>(Wih, Whh, bih, bhh, Wi);
    init_kernel<<<32, 256>>>(x, bi);
    step0_kernel<<<128, 256, 98304>>>(lf, out);
    lstm_kernel<<<128, 256>>>(out);
}

// round 7
// speedup vs baseline: 2.0347x; 2.0347x over previous
#include <cuda_runtime.h>
#include <cstdint>

#define B 256
#define L 128
#define F 256
#define S 512
#define BF (B*F)
#define G4F 1024

// ---- static device scratch (no allocation) ----
__device__ float g_Wc[G4F * F];     // combined W_ih+W_hh, permuted [nf*128+c][k], tf32-rounded
__device__ float g_WihT[G4F * F];   // [(nf*256+k)*128 + c]  (permuted c)
__device__ float g_WhhT[G4F * F];
__device__ float g_WiT[L * F];      // [k*256 + f]
__device__ float g_bc[G4F];         // permuted combined bias
__device__ float g_init[B * F];
__device__ float g_c1[B * F];
__device__ unsigned g_flag[512 * 16 * 8];   // [row t][mb][nf] : d_out row t slice written

__device__ __forceinline__ float sigf(float x) { return 1.0f / (1.0f + expf(-x)); }
__device__ __forceinline__ float tanhfast(float x) {
    float r; asm("tanh.approx.f32 %0, %1;" : "=f"(r) : "f"(x)); return r;
}
__device__ __forceinline__ float sigfast(float x) { return 0.5f * tanhfast(0.5f * x) + 0.5f; }
__device__ __forceinline__ unsigned tf32r(float x) {
    unsigned u; asm("cvt.rna.tf32.f32 %0, %1;" : "=r"(u) : "f"(x)); return u;
}
__device__ __forceinline__ void flag_release(unsigned* p) {
    asm volatile("st.release.gpu.global.u32 [%0], %1;" :: "l"(p), "r"(1u) : "memory");
}
__device__ __forceinline__ void flag_spin(const unsigned* p) {
    unsigned v;
    do { asm volatile("ld.acquire.gpu.global.u32 %0, [%1];" : "=r"(v) : "l"(p) : "memory"); }
    while (v == 0u);
}

__global__ void reset_kernel() {
    g_flag[blockIdx.x * blockDim.x + threadIdx.x] = 0u;
}

// ---- P0: weight prep ----
__global__ void prep_kernel(const float* __restrict__ Wih, const float* __restrict__ Whh,
                            const float* __restrict__ bih, const float* __restrict__ bhh,
                            const float* __restrict__ Wi) {
    int bid = blockIdx.x, tid = threadIdx.x;
    if (bid < 1024) {
        int r = bid, k = tid;
        int g = r >> 8;
        int jj = r & 255;
        int nf = jj >> 5;
        int j  = jj & 31;
        int c  = ((j >> 3) << 5) + (g << 3) + (j & 7);
        float wih = Wih[r * 256 + k];
        float whh = Whh[r * 256 + k];
        g_Wc[(nf * 128 + c) * 256 + k] = __uint_as_float(tf32r(wih + whh));
        g_WihT[(nf * 256 + k) * 128 + c] = wih;
        g_WhhT[(nf * 256 + k) * 128 + c] = whh;
        if (k == 0) g_bc[nf * 128 + c] = bih[r] + bhh[r];
    } else {
        int k = bid - 1024;
        int f = tid;
        g_WiT[k * 256 + f] = Wi[f * 128 + k];
    }
}

// ---- P1: init = elu(x @ Wi.T + bi) ----
__global__ void init_kernel(const float* __restrict__ x, const float* __restrict__ bi) {
    __shared__ float xs[32 * 128];
    int bid = blockIdx.x, tid = threadIdx.x;
    int bt = bid >> 2, ft = bid & 3;
    for (int i = tid; i < 32 * 128; i += 256)
        xs[i] = x[(bt * 32 + (i >> 7)) * 128 + (i & 127)];
    __syncthreads();
    int tx = tid & 15, ty = tid >> 4;
    int b0 = ty * 2;
    int f0 = ft * 64 + tx * 4;
    float acc[2][4] = {};
#pragma unroll 4
    for (int k = 0; k < 128; ++k) {
        float4 w = *(const float4*)&g_WiT[k * 256 + f0];
        float x0 = xs[b0 * 128 + k];
        float x1 = xs[(b0 + 1) * 128 + k];
        acc[0][0] += x0 * w.x; acc[0][1] += x0 * w.y; acc[0][2] += x0 * w.z; acc[0][3] += x0 * w.w;
        acc[1][0] += x1 * w.x; acc[1][1] += x1 * w.y; acc[1][2] += x1 * w.z; acc[1][3] += x1 * w.w;
    }
#pragma unroll
    for (int r = 0; r < 2; ++r)
#pragma unroll
        for (int cc = 0; cc < 4; ++cc) {
            float v = acc[r][cc] + bi[f0 + cc];
            v = (v > 0.0f) ? v : expm1f(v);
            g_init[(bt * 32 + b0 + r) * 256 + f0 + cc] = v;
        }
}

// ---- P2: step 0 (inp = last_feat, h = c = init) ----
__global__ void step0_kernel(const float* __restrict__ lf, float* __restrict__ d_out) {
    extern __shared__ float sm[];
    float* lfs = sm;
    float* ins = lfs + 16 * 256;
    float* wih = ins + 16 * 256;
    float* whh = wih + 64 * 128;
    int tid = threadIdx.x;
    int nf = blockIdx.x & 7, mbt = blockIdx.x >> 3;
    for (int i = tid; i < 16 * 256; i += 256) {
        int gi = (mbt * 16 + (i >> 8)) * 256 + (i & 255);
        lfs[i] = lf[gi];
        ins[i] = g_init[gi];
    }
    int tx = tid & 31, ty = tid >> 5;
    int c0 = tx * 4;
    float acc[2][4] = {};
    for (int kc = 0; kc < 4; ++kc) {
        __syncthreads();
        for (int i = tid; i < 64 * 128; i += 256) {
            int k = kc * 64 + (i >> 7), c = i & 127;
            wih[i] = g_WihT[(nf * 256 + k) * 128 + c];
            whh[i] = g_WhhT[(nf * 256 + k) * 128 + c];
        }
        __syncthreads();
#pragma unroll 4
        for (int k = 0; k < 64; ++k) {
            float4 a4 = *(const float4*)&wih[k * 128 + c0];
            float4 b4 = *(const float4*)&whh[k * 128 + c0];
#pragma unroll
            for (int e = 0; e < 2; ++e) {
                int b = ty + 8 * e;
                float lv = lfs[b * 256 + kc * 64 + k];
                float iv = ins[b * 256 + kc * 64 + k];
                acc[e][0] += lv * a4.x + iv * b4.x;
                acc[e][1] += lv * a4.y + iv * b4.y;
                acc[e][2] += lv * a4.z + iv * b4.z;
                acc[e][3] += lv * a4.w + iv * b4.w;
            }
        }
    }
    __syncthreads();
    float* gss = lfs;
#pragma unroll
    for (int e = 0; e < 2; ++e)
#pragma unroll
        for (int cc = 0; cc < 4; ++cc)
            gss[(ty + 8 * e) * 132 + c0 + cc] = acc[e][cc];
    __syncthreads();
#pragma unroll
    for (int e2 = 0; e2 < 2; ++e2) {
        int li = tid + 256 * e2;
        int b = li >> 5, j = li & 31;
        int cb = ((j >> 3) << 5) + (j & 7);
        float iv = gss[b * 132 + cb]      + g_bc[nf * 128 + cb];
        float fv = gss[b * 132 + cb + 8]  + g_bc[nf * 128 + cb + 8];
        float gv = gss[b * 132 + cb + 16] + g_bc[nf * 128 + cb + 16];
        float ov = gss[b * 132 + cb + 24] + g_bc[nf * 128 + cb + 24];
        float cp = ins[b * 256 + nf * 32 + j];
        float cn = sigf(fv) * cp + sigf(iv) * tanhf(gv);
        float hn = sigf(ov) * tanhf(cn);
        int gi = (mbt * 16 + b) * 256 + nf * 32 + j;
        g_c1[gi] = cn;
        d_out[gi] = hn;
    }
}

// ---- tf32 mma helper ----
__device__ __forceinline__ void mma8(float* d, const unsigned* a, unsigned b0, unsigned b1) {
    asm volatile(
        "mma.sync.aligned.m16n8k8.row.col.f32.tf32.tf32.f32 "
        "{%0,%1,%2,%3}, {%4,%5,%6,%7}, {%8,%9}, {%0,%1,%2,%3};"
        : "+f"(d[0]), "+f"(d[1]), "+f"(d[2]), "+f"(d[3])
        : "r"(a[0]), "r"(a[1]), "r"(a[2]), "r"(a[3]), "r"(b0), "r"(b1));
}

// ---- P3: persistent recurrence, t = 1..511 ----
// 128 CTAs x 256 thr, NO clusters. mb = bid>>3 (16 rows), nf = bid&7 (128 gate cols).
// 8 warps = 4 col-groups x 2 k-halves. ks=1 warps stage next h while ks=0 do elementwise.
// Sync via per-producer t-indexed flags in L2 (st.release / ld.acquire).
__global__ void __launch_bounds__(256, 1)
lstm_kernel(float* __restrict__ d_out) {
    __shared__ float hs[16 * 260];     // h tile (tf32 in fp32 slots), mma layout
    __shared__ float red[128 * 20];    // k-split partials

    int tid = threadIdx.x;
    int nf = blockIdx.x & 7, mb = blockIdx.x >> 3;
    int warp = tid >> 5, lane = tid & 31;
    int cg = warp & 3, ks = warp >> 2;
    int gID = lane >> 2, tig = lane & 3;

    // B fragments in registers: warp covers cols [cg*32,+32), k in [ks*128,+128)
    unsigned breg[4][16][2];
#pragma unroll
    for (int nt = 0; nt < 4; ++nt)
#pragma unroll
        for (int kb = 0; kb < 16; ++kb) {
            const float* wp = &g_Wc[(nf * 128 + cg * 32 + nt * 8 + gID) * 256 + ks * 128 + kb * 8 + tig];
            breg[nt][kb][0] = __float_as_uint(wp[0]);
            breg[nt][kb][1] = __float_as_uint(wp[4]);
        }

    float bias[4][2];
#pragma unroll
    for (int nt = 0; nt < 4; ++nt) {
        float b0 = g_bc[nf * 128 + cg * 32 + nt * 8 + 2 * tig];
        float b1 = g_bc[nf * 128 + cg * 32 + nt * 8 + 2 * tig + 1];
        bias[nt][0] = ks ? 0.0f : b0;
        bias[nt][1] = ks ? 0.0f : b1;
    }

    float creg[4];
    if (ks == 0) {
#pragma unroll
        for (int rh = 0; rh < 2; ++rh)
#pragma unroll
            for (int ff = 0; ff < 2; ++ff)
                creg[rh * 2 + ff] =
                    g_c1[(mb * 16 + gID + rh * 8) * 256 + nf * 32 + cg * 8 + 2 * tig + ff];
    }

    // prologue: stage h_1 (d_out row 0, by step0; stream-ordered, no flags)
    {
        const float* hsrc = d_out + (size_t)mb * 4096;
#pragma unroll
        for (int i = tid * 4; i < 4096; i += 1024) {
            float4 v = *(const float4*)(hsrc + i);
            v.x = __uint_as_float(tf32r(v.x)); v.y = __uint_as_float(tf32r(v.y));
            v.z = __uint_as_float(tf32r(v.z)); v.w = __uint_as_float(tf32r(v.w));
            *(float4*)&hs[(i >> 8) * 260 + (i & 255)] = v;
        }
    }
    __syncthreads();

    for (int t = 1; t < 512; ++t) {
        // ---- mma: gates(16x32 this cg) += hs(k-half) @ Wc^T ----
        float acc[4][4];
#pragma unroll
        for (int nt = 0; nt < 4; ++nt) {
            acc[nt][0] = bias[nt][0]; acc[nt][1] = bias[nt][1];
            acc[nt][2] = bias[nt][0]; acc[nt][3] = bias[nt][1];
        }
#pragma unroll
        for (int kb = 0; kb < 16; ++kb) {
            int k0 = ks * 128 + kb * 8;
            unsigned a[4];
            a[0] = __float_as_uint(hs[gID * 260 + k0 + tig]);
            a[1] = __float_as_uint(hs[(gID + 8) * 260 + k0 + tig]);
            a[2] = __float_as_uint(hs[gID * 260 + k0 + 4 + tig]);
            a[3] = __float_as_uint(hs[(gID + 8) * 260 + k0 + 4 + tig]);
#pragma unroll
            for (int nt = 0; nt < 4; ++nt)
                mma8(acc[nt], a, breg[nt][kb][0], breg[nt][kb][1]);
        }
        if (ks == 1) {
            float* rp = &red[(cg * 32 + lane) * 20];
#pragma unroll
            for (int nt = 0; nt < 4; ++nt)
                *(float4*)(rp + nt * 4) = make_float4(acc[nt][0], acc[nt][1], acc[nt][2], acc[nt][3]);
        }
        __syncthreads();   // SYNC A: all hs reads done; red visible

        if (ks == 1) {
            // ---- stage h_{t+1} remote slices (7 of them) concurrently with elementwise ----
            if (t < 511) {
                const float* base = d_out + (size_t)t * BF + (size_t)mb * 4096;
                int row = lane >> 1;
                int colb = (lane & 1) * 16;
                for (int jj = warp - 4; jj < 7; jj += 4) {
                    int j = (nf + 1 + jj) & 7;
                    flag_spin(&g_flag[(t * 16 + mb) * 8 + j]);
#pragma unroll
                    for (int v4 = 0; v4 < 4; ++v4) {
                        int col = colb + v4 * 4;
                        float4 v = *(const float4*)(base + row * 256 + j * 32 + col);
                        v.x = __uint_as_float(tf32r(v.x)); v.y = __uint_as_float(tf32r(v.y));
                        v.z = __uint_as_float(tf32r(v.z)); v.w = __uint_as_float(tf32r(v.w));
                        *(float4*)&hs[row * 260 + j * 32 + col] = v;
                    }
                }
            }
        } else {
            // ---- reduce + elementwise + own-slice STS + STG + flag release ----
            const float* rp = &red[(cg * 32 + lane) * 20];
#pragma unroll
            for (int nt = 0; nt < 4; ++nt) {
                float4 r4 = *(const float4*)(rp + nt * 4);
                acc[nt][0] += r4.x; acc[nt][1] += r4.y;
                acc[nt][2] += r4.z; acc[nt][3] += r4.w;
            }
            float hn[2][2];
#pragma unroll
            for (int rh = 0; rh < 2; ++rh)
#pragma unroll
                for (int ff = 0; ff < 2; ++ff) {
                    int q = rh * 2 + ff;
                    float cn = sigfast(acc[1][q]) * creg[q] + sigfast(acc[0][q]) * tanhfast(acc[2][q]);
                    hn[rh][ff] = sigfast(acc[3][q]) * tanhfast(cn);
                    creg[q] = cn;
                }
            // own slice straight into hs (tf32-rounded), no L2 round trip
            if (t < 511) {
#pragma unroll
                for (int rh = 0; rh < 2; ++rh)
                    *(float2*)&hs[(gID + rh * 8) * 260 + nf * 32 + cg * 8 + 2 * tig] =
                        make_float2(__uint_as_float(tf32r(hn[rh][0])),
                                    __uint_as_float(tf32r(hn[rh][1])));
            }
            // fp32 h to output (also serves peers' staging reads)
            float* dst = d_out + (size_t)t * BF + (size_t)mb * 4096;
#pragma unroll
            for (int rh = 0; rh < 2; ++rh)
                *(float2*)(dst + (gID + rh * 8) * 256 + nf * 32 + cg * 8 + 2 * tig) =
                    make_float2(hn[rh][0], hn[rh][1]);

            asm volatile("bar.sync 1, 128;" ::: "memory");   // ks=0 stores done
            if (tid == 0 && t < 511)
                flag_release(&g_flag[(t * 16 + mb) * 8 + nf]);
        }

        __syncthreads();   // SYNC B: hs(t+1) fully staged
    }
}

extern "C" void kernel_launch(void* const* d_in, const int* in_sizes, int n_in,
                              void* d_out, int out_size) {
    const float* x   = (const float*)d_in[0];
    const float* lf  = (const float*)d_in[1];
    const float* Wi  = (const float*)d_in[2];
    const float* bi  = (const float*)d_in[3];
    const float* Wih = (const float*)d_in[4];
    const float* Whh = (const float*)d_in[5];
    const float* bih = (const float*)d_in[6];
    const float* bhh = (const float*)d_in[7];
    float* out = (float*)d_out;

    cudaFuncSetAttribute(step0_kernel, cudaFuncAttributeMaxDynamicSharedMemorySize, 98304);

    reset_kernel<<<64, 1024>>>();
    prep_kernel<<<1152, 256>>>(Wih, Whh, bih, bhh, Wi);
    init_kernel<<<32, 256>>>(x, bi);
    step0_kernel<<<128, 256, 98304>>>(lf, out);
    lstm_kernel<<<128, 256>>>(out);
}